// round 2
// baseline (speedup 1.0000x reference)
#include <cuda_runtime.h>
#include <math.h>

#define NG    64
#define ATOMS 32
#define NN    2048
#define HID   128
#define FEAT  64
#define BINS  32
#define OUTD  64
#define D0    106
#define D0P   108
#define D1    85
#define D1P   88

// ---------------- scratch (device globals; no allocations allowed) ----------------
__device__ float d_emb[NG * HID];
__device__ float d_isl[NG];
__device__ float d_x[NN * HID];
__device__ float d_q[NN * HID];
__device__ float d_k[NN * HID];
__device__ float d_v[NN * HID];
__device__ float d_vals[NN * HID];

// ---------------- K0: embedding rows + per-graph 1/sqrt(len) ----------------
__global__ void k_emb(const float* __restrict__ next_type,
                      const float* __restrict__ W_emb,
                      const int* __restrict__ batch) {
    int g = blockIdx.x, t = threadIdx.x;   // 128 threads
    __shared__ float nt[FEAT];
    __shared__ int sc[128];
    if (t < FEAT) nt[t] = next_type[g * FEAT + t];
    __syncthreads();
    const float* w = W_emb + t * FEAT;
    float acc = 0.f;
#pragma unroll
    for (int f = 0; f < FEAT; f++) acc += nt[f] * w[f];
    d_emb[g * HID + t] = acc;
    int cnt = 0;
    for (int i = t; i < NN; i += 128) cnt += (batch[i] == g) ? 1 : 0;
    sc[t] = cnt;
    __syncthreads();
    for (int s = 64; s > 0; s >>= 1) {
        if (t < s) sc[t] += sc[t + s];
        __syncthreads();
    }
    if (t == 0) d_isl[g] = rsqrtf((float)sc[0]);
}

// ---------------- K1: x = h * emb[batch] ----------------
__global__ void k_x(const float* __restrict__ h, const int* __restrict__ batch) {
    int idx = blockIdx.x * blockDim.x + threadIdx.x;
    int row = idx >> 7;
    d_x[idx] = h[idx] * d_emb[batch[row] * HID + (idx & 127)];
}

// ---------------- K2: qkv = x @ W_qkv^T + b, routed to q/k/v ----------------
// 64x64 output tile per block, K=128 in two 64-chunks, k-major smem, 4x4 microtile
__global__ void k_qkv(const float* __restrict__ W_qkv, const float* __restrict__ b_qkv) {
    __shared__ float Xs[64 * 64];
    __shared__ float Ws[64 * 64];
    int tid = threadIdx.x;
    int rb = blockIdx.y * 64;
    int cb = blockIdx.x * 64;        // output neuron base (0..320)
    int ty = tid >> 4, tx = tid & 15;
    float acc[4][4] = {};

    for (int k0 = 0; k0 < HID; k0 += 64) {
#pragma unroll
        for (int v = 0; v < 4; v++) {
            int lin = tid + v * 256;          // 0..1023
            int r = lin >> 4;                 // 0..63
            int kv = lin & 15;
            float4 a = *(const float4*)&d_x[(rb + r) * HID + k0 + kv * 4];
            Xs[(kv * 4 + 0) * 64 + r] = a.x;
            Xs[(kv * 4 + 1) * 64 + r] = a.y;
            Xs[(kv * 4 + 2) * 64 + r] = a.z;
            Xs[(kv * 4 + 3) * 64 + r] = a.w;
            float4 b = *(const float4*)&W_qkv[(cb + r) * HID + k0 + kv * 4];
            Ws[(kv * 4 + 0) * 64 + r] = b.x;
            Ws[(kv * 4 + 1) * 64 + r] = b.y;
            Ws[(kv * 4 + 2) * 64 + r] = b.z;
            Ws[(kv * 4 + 3) * 64 + r] = b.w;
        }
        __syncthreads();
#pragma unroll 8
        for (int k = 0; k < 64; k++) {
            float4 a = *(const float4*)&Xs[k * 64 + ty * 4];
            float4 b = *(const float4*)&Ws[k * 64 + tx * 4];
            float av[4] = {a.x, a.y, a.z, a.w};
            float bv[4] = {b.x, b.y, b.z, b.w};
#pragma unroll
            for (int i = 0; i < 4; i++)
#pragma unroll
                for (int j = 0; j < 4; j++) acc[i][j] += av[i] * bv[j];
        }
        __syncthreads();
    }

    int which = cb >> 7;                    // whole block maps to exactly one of q/k/v
    int col0 = (cb & 127) + tx * 4;
    float* outb = (which == 0) ? d_q : ((which == 1) ? d_k : d_v);
    float4 bv4;
    bv4.x = b_qkv[cb + tx * 4 + 0];
    bv4.y = b_qkv[cb + tx * 4 + 1];
    bv4.z = b_qkv[cb + tx * 4 + 2];
    bv4.w = b_qkv[cb + tx * 4 + 3];
#pragma unroll
    for (int i = 0; i < 4; i++) {
        int row = rb + ty * 4 + i;
        float4 o;
        o.x = acc[i][0] + bv4.x;
        o.y = acc[i][1] + bv4.y;
        o.z = acc[i][2] + bv4.z;
        o.w = acc[i][3] + bv4.w;
        *(float4*)&outb[row * HID + col0] = o;
    }
}

// ---------------- K3: per-graph fused attention ----------------
// smem floats: Qt[128][32]=4096, Kt[128][32]=4096, V[32][128]=4096, L[32][32]=1024,
//              Wg 128, pos 96, gate 32, wt 32, total 13604
__global__ void k_attn(const float* __restrict__ pos,
                       const float* __restrict__ W_t, const float* __restrict__ b_t,
                       const float* __restrict__ W_g, const float* __restrict__ b_g) {
    extern __shared__ float sm[];
    float* sQt  = sm;             // [128][32]
    float* sKt  = sm + 4096;      // [128][32]
    float* sV   = sm + 8192;      // [32][128]
    float* sL   = sm + 12288;     // [32][32]
    float* sWg  = sm + 13312;     // 128
    float* sPos = sm + 13440;     // 96
    float* sGate= sm + 13536;     // 32
    float* sWt  = sm + 13568;     // 32

    int g = blockIdx.x, tid = threadIdx.x;
    int base = g * ATOMS;

#pragma unroll
    for (int v = 0; v < 4; v++) {
        int lin = tid + v * 256;  // 0..1023 float4 slots per tile
        int r = lin >> 5;         // 0..31
        int kv = lin & 31;        // 0..31 (float4 index over 128)
        float4 qa = *(const float4*)&d_q[(base + r) * HID + kv * 4];
        sQt[(kv * 4 + 0) * 32 + r] = qa.x;
        sQt[(kv * 4 + 1) * 32 + r] = qa.y;
        sQt[(kv * 4 + 2) * 32 + r] = qa.z;
        sQt[(kv * 4 + 3) * 32 + r] = qa.w;
        float4 ka = *(const float4*)&d_k[(base + r) * HID + kv * 4];
        sKt[(kv * 4 + 0) * 32 + r] = ka.x;
        sKt[(kv * 4 + 1) * 32 + r] = ka.y;
        sKt[(kv * 4 + 2) * 32 + r] = ka.z;
        sKt[(kv * 4 + 3) * 32 + r] = ka.w;
        *(float4*)&sV[r * 128 + kv * 4] = *(const float4*)&d_v[(base + r) * HID + kv * 4];
    }
    if (tid < 128) sWg[tid] = W_g[tid];
    if (tid < 96) sPos[tid] = pos[base * 3 + tid];
    if (tid < 32) sWt[tid] = W_t[tid];
    __syncthreads();

    int w = tid >> 5, lane = tid & 31;
    float invs = d_isl[g];
    float bgv = b_g[0];

    // gate: each warp handles 4 rows
#pragma unroll
    for (int rr = 0; rr < 4; rr++) {
        int row = w * 4 + rr;
        const float* xr = d_x + (base + row) * HID;
        float p = 0.f;
#pragma unroll
        for (int k = lane; k < HID; k += 32) p += xr[k] * sWg[k];
#pragma unroll
        for (int o = 16; o; o >>= 1) p += __shfl_xor_sync(~0u, p, o);
        if (lane == 0) sGate[row] = 1.f / (1.f + __expf(-(p + bgv)));
    }

    // logits: 2x2 microtile of (i,j) pairs
    int ty = tid >> 4, tx = tid & 15;
    int i0 = ty * 2, j0 = tx * 2;
    float qk00 = 0.f, qk01 = 0.f, qk10 = 0.f, qk11 = 0.f;
#pragma unroll 4
    for (int k = 0; k < HID; k++) {
        float2 qa = *(const float2*)&sQt[k * 32 + i0];
        float2 kb = *(const float2*)&sKt[k * 32 + j0];
        qk00 += qa.x * kb.x; qk01 += qa.x * kb.y;
        qk10 += qa.y * kb.x; qk11 += qa.y * kb.y;
    }
    float btv = b_t[0];
    float qkv_[2][2] = {{qk00, qk01}, {qk10, qk11}};
#pragma unroll
    for (int ii = 0; ii < 2; ii++) {
#pragma unroll
        for (int jj = 0; jj < 2; jj++) {
            int i = i0 + ii, j = j0 + jj;
            float dx = sPos[i * 3 + 0] - sPos[j * 3 + 0];
            float dy = sPos[i * 3 + 1] - sPos[j * 3 + 1];
            float dz = sPos[i * 3 + 2] - sPos[j * 3 + 2];
            float d = sqrtf(fmaxf(dx * dx + dy * dy + dz * dz, 1e-12f));
            float t = btv;
#pragma unroll
            for (int b = 0; b < BINS; b++) {
                float diff = d - (float)b * (10.f / 31.f);
                t += __expf(-10.f * diff * diff) * sWt[b];
            }
            sL[i * 32 + j] = qkv_[ii][jj] * invs + t;
        }
    }
    __syncthreads();

    // softmax: warp w handles rows w, w+8, w+16, w+24 (32 lanes == 32 cols)
#pragma unroll
    for (int rr = 0; rr < 4; rr++) {
        int i = w + rr * 8;
        float vv = sL[i * 32 + lane];
        float m = vv;
#pragma unroll
        for (int o = 16; o; o >>= 1) m = fmaxf(m, __shfl_xor_sync(~0u, m, o));
        float e = __expf(vv - m);
        float s = e;
#pragma unroll
        for (int o = 16; o; o >>= 1) s += __shfl_xor_sync(~0u, s, o);
        sL[i * 32 + lane] = e / s;
    }
    __syncthreads();

    // out = (attn @ V) * gate + x : 2 rows x 4 cols microtiles, 2 slots/thread
#pragma unroll
    for (int slot = 0; slot < 2; slot++) {
        int sid = tid + slot * 256;   // 0..511
        int rg = sid >> 5;            // 0..15
        int cg = sid & 31;            // 0..31
        int ir = rg * 2, c0 = cg * 4;
        float a00 = 0.f, a01 = 0.f, a02 = 0.f, a03 = 0.f;
        float a10 = 0.f, a11 = 0.f, a12 = 0.f, a13 = 0.f;
#pragma unroll 4
        for (int j = 0; j < 32; j++) {
            float p0 = sL[ir * 32 + j];
            float p1 = sL[(ir + 1) * 32 + j];
            float4 vv = *(const float4*)&sV[j * 128 + c0];
            a00 += p0 * vv.x; a01 += p0 * vv.y; a02 += p0 * vv.z; a03 += p0 * vv.w;
            a10 += p1 * vv.x; a11 += p1 * vv.y; a12 += p1 * vv.z; a13 += p1 * vv.w;
        }
        {
            float gg = sGate[ir];
            float4 xr = *(const float4*)&d_x[(base + ir) * HID + c0];
            float4 o;
            o.x = a00 * gg + xr.x; o.y = a01 * gg + xr.y;
            o.z = a02 * gg + xr.z; o.w = a03 * gg + xr.w;
            *(float4*)&d_vals[(base + ir) * HID + c0] = o;
        }
        {
            float gg = sGate[ir + 1];
            float4 xr = *(const float4*)&d_x[(base + ir + 1) * HID + c0];
            float4 o;
            o.x = a10 * gg + xr.x; o.y = a11 * gg + xr.y;
            o.z = a12 * gg + xr.z; o.w = a13 * gg + xr.w;
            *(float4*)&d_vals[(base + ir + 1) * HID + c0] = o;
        }
    }
}

// ---------------- K4: fused dense head + log_softmax ----------------
// per block: 16 rows. smem floats: W0 13824, W1 9328, W2 5440, A0 2048,
// Y0 1696, Y1 1360, Y2 1024, biases 255 -> total 34975 floats (~137 KB)
__global__ void k_dense(const float* __restrict__ Wd0, const float* __restrict__ bd0,
                        const float* __restrict__ Wd1, const float* __restrict__ bd1,
                        const float* __restrict__ Wd2, const float* __restrict__ bd2,
                        float* __restrict__ out) {
    extern __shared__ float sm[];
    float* W0 = sm;             // [128][108] k-major
    float* W1 = sm + 13824;     // [106][88]
    float* W2 = sm + 23152;     // [85][64]
    float* A0 = sm + 28592;     // [128][16]
    float* Y0 = sm + 30640;     // [106][16]
    float* Y1 = sm + 32336;     // [85][16]
    float* Y2 = sm + 33696;     // [16][64]
    float* B0 = sm + 34720;     // 106
    float* B1 = sm + 34826;     // 85
    float* B2 = sm + 34911;     // 64

    int tid = threadIdx.x;
    int rowbase = blockIdx.x * 16;

    for (int idx = tid; idx < D0 * HID; idx += 256) {
        int o = idx >> 7, k = idx & 127;
        W0[k * D0P + o] = Wd0[idx];
    }
    for (int idx = tid; idx < 2 * HID; idx += 256) {
        int k = idx >> 1;
        W0[k * D0P + D0 + (idx & 1)] = 0.f;
    }
    for (int idx = tid; idx < D1 * D0; idx += 256) {
        int o = idx / D0, k = idx - o * D0;
        W1[k * D1P + o] = Wd1[idx];
    }
    for (int idx = tid; idx < 3 * D0; idx += 256) {
        int k = idx / 3;
        W1[k * D1P + D1 + (idx % 3)] = 0.f;
    }
    for (int idx = tid; idx < OUTD * D1; idx += 256) {
        int o = idx / D1, k = idx - o * D1;
        W2[k * OUTD + o] = Wd2[idx];
    }
    for (int idx = tid; idx < 16 * HID; idx += 256) {
        int r = idx >> 7, k = idx & 127;
        A0[k * 16 + r] = d_vals[(rowbase + r) * HID + k];
    }
    if (tid < D0) B0[tid] = bd0[tid];
    if (tid < D1) B1[tid] = bd1[tid];
    if (tid < OUTD) B2[tid] = bd2[tid];
    __syncthreads();

    // stage 0: 128 -> 106 (SiLU). 8 rowgroups x 27 colgroups = 216 threads
    if (tid < 216) {
        int rg = tid / 27, cg = tid % 27;
        int r0 = rg * 2, o0 = cg * 4;
        float a0c[4] = {}, a1c[4] = {};
#pragma unroll 4
        for (int k = 0; k < HID; k++) {
            float2 a = *(const float2*)&A0[k * 16 + r0];
            float4 wv = *(const float4*)&W0[k * D0P + o0];
            a0c[0] += a.x * wv.x; a0c[1] += a.x * wv.y; a0c[2] += a.x * wv.z; a0c[3] += a.x * wv.w;
            a1c[0] += a.y * wv.x; a1c[1] += a.y * wv.y; a1c[2] += a.y * wv.z; a1c[3] += a.y * wv.w;
        }
#pragma unroll
        for (int oo = 0; oo < 4; oo++) {
            int o = o0 + oo;
            if (o < D0) {
                float z0 = a0c[oo] + B0[o];
                float z1 = a1c[oo] + B0[o];
                Y0[o * 16 + r0]     = z0 / (1.f + __expf(-z0));
                Y0[o * 16 + r0 + 1] = z1 / (1.f + __expf(-z1));
            }
        }
    }
    __syncthreads();

    // stage 1: 106 -> 85 (SiLU). 8 x 22 = 176 threads
    if (tid < 176) {
        int rg = tid / 22, cg = tid % 22;
        int r0 = rg * 2, o0 = cg * 4;
        float a0c[4] = {}, a1c[4] = {};
#pragma unroll 2
        for (int k = 0; k < D0; k++) {
            float2 a = *(const float2*)&Y0[k * 16 + r0];
            float4 wv = *(const float4*)&W1[k * D1P + o0];
            a0c[0] += a.x * wv.x; a0c[1] += a.x * wv.y; a0c[2] += a.x * wv.z; a0c[3] += a.x * wv.w;
            a1c[0] += a.y * wv.x; a1c[1] += a.y * wv.y; a1c[2] += a.y * wv.z; a1c[3] += a.y * wv.w;
        }
#pragma unroll
        for (int oo = 0; oo < 4; oo++) {
            int o = o0 + oo;
            if (o < D1) {
                float z0 = a0c[oo] + B1[o];
                float z1 = a1c[oo] + B1[o];
                Y1[o * 16 + r0]     = z0 / (1.f + __expf(-z0));
                Y1[o * 16 + r0 + 1] = z1 / (1.f + __expf(-z1));
            }
        }
    }
    __syncthreads();

    // stage 2: 85 -> 64 (linear). 8 x 16 = 128 threads
    if (tid < 128) {
        int rg = tid >> 4, cg = tid & 15;
        int r0 = rg * 2, o0 = cg * 4;
        float a0c[4] = {}, a1c[4] = {};
#pragma unroll 2
        for (int k = 0; k < D1; k++) {
            float2 a = *(const float2*)&Y1[k * 16 + r0];
            float4 wv = *(const float4*)&W2[k * OUTD + o0];
            a0c[0] += a.x * wv.x; a0c[1] += a.x * wv.y; a0c[2] += a.x * wv.z; a0c[3] += a.x * wv.w;
            a1c[0] += a.y * wv.x; a1c[1] += a.y * wv.y; a1c[2] += a.y * wv.z; a1c[3] += a.y * wv.w;
        }
#pragma unroll
        for (int oo = 0; oo < 4; oo++) {
            int o = o0 + oo;
            Y2[r0 * OUTD + o]       = a0c[oo] + B2[o];
            Y2[(r0 + 1) * OUTD + o] = a1c[oo] + B2[o];
        }
    }
    __syncthreads();

    // log_softmax over 64 cols: 8 warps x 2 rows
    int w = tid >> 5, lane = tid & 31;
#pragma unroll
    for (int rr = 0; rr < 2; rr++) {
        int r = w * 2 + rr;
        float v0 = Y2[r * OUTD + lane];
        float v1 = Y2[r * OUTD + 32 + lane];
        float m = fmaxf(v0, v1);
#pragma unroll
        for (int o = 16; o; o >>= 1) m = fmaxf(m, __shfl_xor_sync(~0u, m, o));
        float s = __expf(v0 - m) + __expf(v1 - m);
#pragma unroll
        for (int o = 16; o; o >>= 1) s += __shfl_xor_sync(~0u, s, o);
        float ls = logf(s) + m;
        out[(rowbase + r) * OUTD + lane] = v0 - ls;
        out[(rowbase + r) * OUTD + 32 + lane] = v1 - ls;
    }
}

// ---------------- launch ----------------
extern "C" void kernel_launch(void* const* d_in, const int* in_sizes, int n_in,
                              void* d_out, int out_size) {
    const float* h     = (const float*)d_in[0];
    const float* pos   = (const float*)d_in[1];
    const float* nt    = (const float*)d_in[2];
    const int*   batch = (const int*)d_in[3];
    const float* W_emb = (const float*)d_in[4];
    const float* W_qkv = (const float*)d_in[5];
    const float* b_qkv = (const float*)d_in[6];
    // d_in[7]=W_b, d_in[8]=b_b : per-row bias, mathematically drops out of softmax
    const float* W_g   = (const float*)d_in[9];
    const float* b_g   = (const float*)d_in[10];
    const float* W_t   = (const float*)d_in[11];
    const float* b_t   = (const float*)d_in[12];
    const float* W_d0  = (const float*)d_in[13];
    const float* b_d0  = (const float*)d_in[14];
    const float* W_d1  = (const float*)d_in[15];
    const float* b_d1  = (const float*)d_in[16];
    const float* W_d2  = (const float*)d_in[17];
    const float* b_d2  = (const float*)d_in[18];
    float* out = (float*)d_out;

    cudaFuncSetAttribute(k_attn, cudaFuncAttributeMaxDynamicSharedMemorySize, 56 * 1024);
    cudaFuncSetAttribute(k_dense, cudaFuncAttributeMaxDynamicSharedMemorySize, 141 * 1024);

    k_emb<<<NG, 128>>>(nt, W_emb, batch);
    k_x<<<(NN * HID) / 256, 256>>>(h, batch);
    k_qkv<<<dim3(6, 32), 256>>>(W_qkv, b_qkv);
    k_attn<<<NG, 256, 13604 * 4>>>(pos, W_t, b_t, W_g, b_g);
    k_dense<<<NN / 16, 256, 34975 * 4>>>(W_d0, b_d0, W_d1, b_d1, W_d2, b_d2, out);
}

// round 3
// speedup vs baseline: 1.1775x; 1.1775x over previous
#include <cuda_runtime.h>
#include <math.h>

#define NG    64
#define ATOMS 32
#define NN    2048
#define HID   128
#define FEAT  64
#define BINS  32
#define OUTD  64
#define D0    106
#define D0P   108
#define D1    85
#define D1P   88

// ---------------- scratch (device globals; no allocations allowed) ----------------
__device__ float d_isl[NG];
__device__ float d_x[NN * HID];
__device__ float d_q[NN * HID];
__device__ float d_k[NN * HID];
__device__ float d_v[NN * HID];
__device__ float d_vals[NN * HID];

// ---------------- K0: fused embedding + x = h * emb[batch] + 1/sqrt(len) -------
__global__ void k_prep(const float* __restrict__ h,
                       const float* __restrict__ next_type,
                       const float* __restrict__ W_emb,
                       const int* __restrict__ batch) {
    __shared__ float nt[FEAT];
    __shared__ float emb[HID];
    __shared__ int sc[256];
    int g = blockIdx.x, t = threadIdx.x;   // 256 threads
    int base = g * ATOMS;

    if (t < FEAT) nt[t] = next_type[g * FEAT + t];
    __syncthreads();
    if (t < HID) {
        const float* w = W_emb + t * FEAT;
        float acc = 0.f;
#pragma unroll
        for (int f = 0; f < FEAT; f++) acc += nt[f] * w[f];
        emb[t] = acc;
    }
    int cnt = 0;
#pragma unroll
    for (int i = t; i < NN; i += 256) cnt += (batch[i] == g) ? 1 : 0;
    sc[t] = cnt;
    __syncthreads();
    for (int s = 128; s > 0; s >>= 1) {
        if (t < s) sc[t] += sc[t + s];
        __syncthreads();
    }
    if (t == 0) d_isl[g] = rsqrtf((float)sc[0]);

    // x: 32 rows x 128 cols = 1024 float4 slots, 4 per thread
#pragma unroll
    for (int v = 0; v < 4; v++) {
        int lin = t + v * 256;
        int r = lin >> 5, kv = lin & 31;
        float4 hv = *(const float4*)&h[(base + r) * HID + kv * 4];
        float4 ev = *(const float4*)&emb[kv * 4];
        float4 o;
        o.x = hv.x * ev.x; o.y = hv.y * ev.y; o.z = hv.z * ev.z; o.w = hv.w * ev.w;
        *(float4*)&d_x[(base + r) * HID + kv * 4] = o;
    }
}

// ---------------- K1: qkv = x @ W_qkv^T + b, routed to q/k/v ----------------
__global__ void k_qkv(const float* __restrict__ W_qkv, const float* __restrict__ b_qkv) {
    __shared__ float Xs[64 * 64];
    __shared__ float Ws[64 * 64];
    int tid = threadIdx.x;
    int rb = blockIdx.y * 64;
    int cb = blockIdx.x * 64;
    int ty = tid >> 4, tx = tid & 15;
    float acc[4][4] = {};

    for (int k0 = 0; k0 < HID; k0 += 64) {
#pragma unroll
        for (int v = 0; v < 4; v++) {
            int lin = tid + v * 256;
            int r = lin >> 4;
            int kv = lin & 15;
            float4 a = *(const float4*)&d_x[(rb + r) * HID + k0 + kv * 4];
            Xs[(kv * 4 + 0) * 64 + r] = a.x;
            Xs[(kv * 4 + 1) * 64 + r] = a.y;
            Xs[(kv * 4 + 2) * 64 + r] = a.z;
            Xs[(kv * 4 + 3) * 64 + r] = a.w;
            float4 b = *(const float4*)&W_qkv[(cb + r) * HID + k0 + kv * 4];
            Ws[(kv * 4 + 0) * 64 + r] = b.x;
            Ws[(kv * 4 + 1) * 64 + r] = b.y;
            Ws[(kv * 4 + 2) * 64 + r] = b.z;
            Ws[(kv * 4 + 3) * 64 + r] = b.w;
        }
        __syncthreads();
#pragma unroll 8
        for (int k = 0; k < 64; k++) {
            float4 a = *(const float4*)&Xs[k * 64 + ty * 4];
            float4 b = *(const float4*)&Ws[k * 64 + tx * 4];
            float av[4] = {a.x, a.y, a.z, a.w};
            float bv[4] = {b.x, b.y, b.z, b.w};
#pragma unroll
            for (int i = 0; i < 4; i++)
#pragma unroll
                for (int j = 0; j < 4; j++) acc[i][j] += av[i] * bv[j];
        }
        __syncthreads();
    }

    int which = cb >> 7;
    int col0 = (cb & 127) + tx * 4;
    float* outb = (which == 0) ? d_q : ((which == 1) ? d_k : d_v);
    float4 bv4;
    bv4.x = b_qkv[cb + tx * 4 + 0];
    bv4.y = b_qkv[cb + tx * 4 + 1];
    bv4.z = b_qkv[cb + tx * 4 + 2];
    bv4.w = b_qkv[cb + tx * 4 + 3];
#pragma unroll
    for (int i = 0; i < 4; i++) {
        int row = rb + ty * 4 + i;
        float4 o;
        o.x = acc[i][0] + bv4.x;
        o.y = acc[i][1] + bv4.y;
        o.z = acc[i][2] + bv4.z;
        o.w = acc[i][3] + bv4.w;
        *(float4*)&outb[row * HID + col0] = o;
    }
}

// ---------------- K2: fused attention, 2 blocks per graph (16 rows each) --------
// smem floats: Qt[128][16]=2048, Kt[128][32]=4096, V[32][128]=4096, L[16][32]=512,
//              Wg 128, pos 96, gate 16, wt 32 -> 11024 floats (~43 KB)
__global__ void k_attn(const float* __restrict__ pos,
                       const float* __restrict__ W_t, const float* __restrict__ b_t,
                       const float* __restrict__ W_g, const float* __restrict__ b_g) {
    extern __shared__ float sm[];
    float* sQt  = sm;             // [128][16]
    float* sKt  = sm + 2048;      // [128][32]
    float* sV   = sm + 6144;      // [32][128]
    float* sL   = sm + 10240;     // [16][32]
    float* sWg  = sm + 10752;     // 128
    float* sPos = sm + 10880;     // 96
    float* sGate= sm + 10976;     // 16
    float* sWt  = sm + 10992;     // 32

    int bid = blockIdx.x, tid = threadIdx.x;
    int g = bid >> 1, half = bid & 1;
    int base = g * ATOMS;
    int rbase = half * 16;

    // Q rows (16x128): 512 float4 slots, 2 per thread; k-major
#pragma unroll
    for (int v = 0; v < 2; v++) {
        int lin = tid + v * 256;
        int r = lin >> 5, kv = lin & 31;
        float4 qa = *(const float4*)&d_q[(base + rbase + r) * HID + kv * 4];
        sQt[(kv * 4 + 0) * 16 + r] = qa.x;
        sQt[(kv * 4 + 1) * 16 + r] = qa.y;
        sQt[(kv * 4 + 2) * 16 + r] = qa.z;
        sQt[(kv * 4 + 3) * 16 + r] = qa.w;
    }
    // K (k-major) + V (row-major), all 32 rows: 1024 slots, 4 per thread
#pragma unroll
    for (int v = 0; v < 4; v++) {
        int lin = tid + v * 256;
        int r = lin >> 5, kv = lin & 31;
        float4 ka = *(const float4*)&d_k[(base + r) * HID + kv * 4];
        sKt[(kv * 4 + 0) * 32 + r] = ka.x;
        sKt[(kv * 4 + 1) * 32 + r] = ka.y;
        sKt[(kv * 4 + 2) * 32 + r] = ka.z;
        sKt[(kv * 4 + 3) * 32 + r] = ka.w;
        *(float4*)&sV[r * 128 + kv * 4] = *(const float4*)&d_v[(base + r) * HID + kv * 4];
    }
    if (tid < 128) sWg[tid] = W_g[tid];
    if (tid < 96) sPos[tid] = pos[base * 3 + tid];
    if (tid < 32) sWt[tid] = W_t[tid];
    __syncthreads();

    int w = tid >> 5, lane = tid & 31;
    float invs = d_isl[g];
    float bgv = b_g[0];

    // gate: 8 warps x 2 rows
#pragma unroll
    for (int rr = 0; rr < 2; rr++) {
        int row = w * 2 + rr;
        const float* xr = d_x + (base + rbase + row) * HID;
        float p = 0.f;
#pragma unroll
        for (int k = lane; k < HID; k += 32) p += xr[k] * sWg[k];
#pragma unroll
        for (int o = 16; o; o >>= 1) p += __shfl_xor_sync(~0u, p, o);
        if (lane == 0) sGate[row] = 1.f / (1.f + __expf(-(p + bgv)));
    }

    // logits: thread -> (i, {j0, j0+1})
    int i = tid >> 4;            // 0..15 local row
    int j0 = (tid & 15) * 2;
    float qk0 = 0.f, qk1 = 0.f;
#pragma unroll 8
    for (int k = 0; k < HID; k++) {
        float qa = sQt[k * 16 + i];
        float2 kb = *(const float2*)&sKt[k * 32 + j0];
        qk0 += qa * kb.x;
        qk1 += qa * kb.y;
    }
    float btv = b_t[0];
    int gi = rbase + i;          // atom index within graph
    float px = sPos[gi * 3 + 0], py = sPos[gi * 3 + 1], pz = sPos[gi * 3 + 2];
    const float step = 10.f / 31.f;
    float qkp[2] = {qk0, qk1};
#pragma unroll
    for (int jj = 0; jj < 2; jj++) {
        int j = j0 + jj;
        float dx = px - sPos[j * 3 + 0];
        float dy = py - sPos[j * 3 + 1];
        float dz = pz - sPos[j * 3 + 2];
        float d = sqrtf(fmaxf(dx * dx + dy * dy + dz * dz, 1e-12f));
        // 8-bin window around nearest center: dropped bins < 3e-6 relative weight
        int b0 = __float2int_rn(d * (31.f / 10.f));
        int bs = min(max(b0 - 4, 0), 24);
        float t = btv;
#pragma unroll
        for (int bb = 0; bb < 8; bb++) {
            int b = bs + bb;
            float diff = d - (float)b * step;
            t += __expf(-10.f * diff * diff) * sWt[b];
        }
        sL[i * 32 + j] = qkp[jj] * invs + t;
    }
    __syncthreads();

    // softmax: 8 warps x 2 rows (32 lanes == 32 cols)
#pragma unroll
    for (int rr = 0; rr < 2; rr++) {
        int r = w * 2 + rr;
        float vv = sL[r * 32 + lane];
        float m = vv;
#pragma unroll
        for (int o = 16; o; o >>= 1) m = fmaxf(m, __shfl_xor_sync(~0u, m, o));
        float e = __expf(vv - m);
        float s = e;
#pragma unroll
        for (int o = 16; o; o >>= 1) s += __shfl_xor_sync(~0u, s, o);
        sL[r * 32 + lane] = e / s;
    }
    __syncthreads();

    // out = (attn @ V) * gate + x : 2 rows x 4 cols per thread (8x32 groups = 256)
    int rg = tid >> 5, cg = tid & 31;
    int ir = rg * 2, c0 = cg * 4;
    float a00 = 0.f, a01 = 0.f, a02 = 0.f, a03 = 0.f;
    float a10 = 0.f, a11 = 0.f, a12 = 0.f, a13 = 0.f;
#pragma unroll 8
    for (int j = 0; j < 32; j++) {
        float p0 = sL[ir * 32 + j];
        float p1 = sL[(ir + 1) * 32 + j];
        float4 vv = *(const float4*)&sV[j * 128 + c0];
        a00 += p0 * vv.x; a01 += p0 * vv.y; a02 += p0 * vv.z; a03 += p0 * vv.w;
        a10 += p1 * vv.x; a11 += p1 * vv.y; a12 += p1 * vv.z; a13 += p1 * vv.w;
    }
    {
        int grow = base + rbase + ir;
        float gg = sGate[ir];
        float4 xr = *(const float4*)&d_x[grow * HID + c0];
        float4 o;
        o.x = a00 * gg + xr.x; o.y = a01 * gg + xr.y;
        o.z = a02 * gg + xr.z; o.w = a03 * gg + xr.w;
        *(float4*)&d_vals[grow * HID + c0] = o;
        gg = sGate[ir + 1];
        xr = *(const float4*)&d_x[(grow + 1) * HID + c0];
        o.x = a10 * gg + xr.x; o.y = a11 * gg + xr.y;
        o.z = a12 * gg + xr.z; o.w = a13 * gg + xr.w;
        *(float4*)&d_vals[(grow + 1) * HID + c0] = o;
    }
}

// ---------------- K3: fused dense head + log_softmax ----------------
__global__ void k_dense(const float* __restrict__ Wd0, const float* __restrict__ bd0,
                        const float* __restrict__ Wd1, const float* __restrict__ bd1,
                        const float* __restrict__ Wd2, const float* __restrict__ bd2,
                        float* __restrict__ out) {
    extern __shared__ float sm[];
    float* W0 = sm;             // [128][108] k-major
    float* W1 = sm + 13824;     // [106][88]
    float* W2 = sm + 23152;     // [85][64]
    float* A0 = sm + 28592;     // [128][16]
    float* Y0 = sm + 30640;     // [106][16]
    float* Y1 = sm + 32336;     // [85][16]
    float* Y2 = sm + 33696;     // [16][64]
    float* B0 = sm + 34720;     // 106
    float* B1 = sm + 34826;     // 85
    float* B2 = sm + 34911;     // 64

    int tid = threadIdx.x;
    int rowbase = blockIdx.x * 16;

    for (int idx = tid; idx < D0 * HID; idx += 256) {
        int o = idx >> 7, k = idx & 127;
        W0[k * D0P + o] = Wd0[idx];
    }
    for (int idx = tid; idx < 2 * HID; idx += 256) {
        int k = idx >> 1;
        W0[k * D0P + D0 + (idx & 1)] = 0.f;
    }
    for (int idx = tid; idx < D1 * D0; idx += 256) {
        int o = idx / D0, k = idx - o * D0;
        W1[k * D1P + o] = Wd1[idx];
    }
    for (int idx = tid; idx < 3 * D0; idx += 256) {
        int k = idx / 3;
        W1[k * D1P + D1 + (idx % 3)] = 0.f;
    }
    for (int idx = tid; idx < OUTD * D1; idx += 256) {
        int o = idx / D1, k = idx - o * D1;
        W2[k * OUTD + o] = Wd2[idx];
    }
    for (int idx = tid; idx < 16 * HID; idx += 256) {
        int r = idx >> 7, k = idx & 127;
        A0[k * 16 + r] = d_vals[(rowbase + r) * HID + k];
    }
    if (tid < D0) B0[tid] = bd0[tid];
    if (tid < D1) B1[tid] = bd1[tid];
    if (tid < OUTD) B2[tid] = bd2[tid];
    __syncthreads();

    // stage 0: 128 -> 106 (SiLU)
    if (tid < 216) {
        int rg = tid / 27, cg = tid % 27;
        int r0 = rg * 2, o0 = cg * 4;
        float a0c[4] = {}, a1c[4] = {};
#pragma unroll 4
        for (int k = 0; k < HID; k++) {
            float2 a = *(const float2*)&A0[k * 16 + r0];
            float4 wv = *(const float4*)&W0[k * D0P + o0];
            a0c[0] += a.x * wv.x; a0c[1] += a.x * wv.y; a0c[2] += a.x * wv.z; a0c[3] += a.x * wv.w;
            a1c[0] += a.y * wv.x; a1c[1] += a.y * wv.y; a1c[2] += a.y * wv.z; a1c[3] += a.y * wv.w;
        }
#pragma unroll
        for (int oo = 0; oo < 4; oo++) {
            int o = o0 + oo;
            if (o < D0) {
                float z0 = a0c[oo] + B0[o];
                float z1 = a1c[oo] + B0[o];
                Y0[o * 16 + r0]     = z0 / (1.f + __expf(-z0));
                Y0[o * 16 + r0 + 1] = z1 / (1.f + __expf(-z1));
            }
        }
    }
    __syncthreads();

    // stage 1: 106 -> 85 (SiLU)
    if (tid < 176) {
        int rg = tid / 22, cg = tid % 22;
        int r0 = rg * 2, o0 = cg * 4;
        float a0c[4] = {}, a1c[4] = {};
#pragma unroll 2
        for (int k = 0; k < D0; k++) {
            float2 a = *(const float2*)&Y0[k * 16 + r0];
            float4 wv = *(const float4*)&W1[k * D1P + o0];
            a0c[0] += a.x * wv.x; a0c[1] += a.x * wv.y; a0c[2] += a.x * wv.z; a0c[3] += a.x * wv.w;
            a1c[0] += a.y * wv.x; a1c[1] += a.y * wv.y; a1c[2] += a.y * wv.z; a1c[3] += a.y * wv.w;
        }
#pragma unroll
        for (int oo = 0; oo < 4; oo++) {
            int o = o0 + oo;
            if (o < D1) {
                float z0 = a0c[oo] + B1[o];
                float z1 = a1c[oo] + B1[o];
                Y1[o * 16 + r0]     = z0 / (1.f + __expf(-z0));
                Y1[o * 16 + r0 + 1] = z1 / (1.f + __expf(-z1));
            }
        }
    }
    __syncthreads();

    // stage 2: 85 -> 64 (linear)
    if (tid < 128) {
        int rg = tid >> 4, cg = tid & 15;
        int r0 = rg * 2, o0 = cg * 4;
        float a0c[4] = {}, a1c[4] = {};
#pragma unroll 2
        for (int k = 0; k < D1; k++) {
            float2 a = *(const float2*)&Y1[k * 16 + r0];
            float4 wv = *(const float4*)&W2[k * OUTD + o0];
            a0c[0] += a.x * wv.x; a0c[1] += a.x * wv.y; a0c[2] += a.x * wv.z; a0c[3] += a.x * wv.w;
            a1c[0] += a.y * wv.x; a1c[1] += a.y * wv.y; a1c[2] += a.y * wv.z; a1c[3] += a.y * wv.w;
        }
#pragma unroll
        for (int oo = 0; oo < 4; oo++) {
            int o = o0 + oo;
            Y2[r0 * OUTD + o]       = a0c[oo] + B2[o];
            Y2[(r0 + 1) * OUTD + o] = a1c[oo] + B2[o];
        }
    }
    __syncthreads();

    // log_softmax over 64 cols: 8 warps x 2 rows
    int w = tid >> 5, lane = tid & 31;
#pragma unroll
    for (int rr = 0; rr < 2; rr++) {
        int r = w * 2 + rr;
        float v0 = Y2[r * OUTD + lane];
        float v1 = Y2[r * OUTD + 32 + lane];
        float m = fmaxf(v0, v1);
#pragma unroll
        for (int o = 16; o; o >>= 1) m = fmaxf(m, __shfl_xor_sync(~0u, m, o));
        float s = __expf(v0 - m) + __expf(v1 - m);
#pragma unroll
        for (int o = 16; o; o >>= 1) s += __shfl_xor_sync(~0u, s, o);
        float ls = logf(s) + m;
        out[(rowbase + r) * OUTD + lane] = v0 - ls;
        out[(rowbase + r) * OUTD + 32 + lane] = v1 - ls;
    }
}

// ---------------- launch ----------------
extern "C" void kernel_launch(void* const* d_in, const int* in_sizes, int n_in,
                              void* d_out, int out_size) {
    const float* h     = (const float*)d_in[0];
    const float* pos   = (const float*)d_in[1];
    const float* nt    = (const float*)d_in[2];
    const int*   batch = (const int*)d_in[3];
    const float* W_emb = (const float*)d_in[4];
    const float* W_qkv = (const float*)d_in[5];
    const float* b_qkv = (const float*)d_in[6];
    // d_in[7]=W_b, d_in[8]=b_b : per-row bias, drops out of softmax
    const float* W_g   = (const float*)d_in[9];
    const float* b_g   = (const float*)d_in[10];
    const float* W_t   = (const float*)d_in[11];
    const float* b_t   = (const float*)d_in[12];
    const float* W_d0  = (const float*)d_in[13];
    const float* b_d0  = (const float*)d_in[14];
    const float* W_d1  = (const float*)d_in[15];
    const float* b_d1  = (const float*)d_in[16];
    const float* W_d2  = (const float*)d_in[17];
    const float* b_d2  = (const float*)d_in[18];
    float* out = (float*)d_out;

    cudaFuncSetAttribute(k_attn, cudaFuncAttributeMaxDynamicSharedMemorySize, 48 * 1024);
    cudaFuncSetAttribute(k_dense, cudaFuncAttributeMaxDynamicSharedMemorySize, 141 * 1024);

    k_prep<<<NG, 256>>>(h, nt, W_emb, batch);
    k_qkv<<<dim3(6, 32), 256>>>(W_qkv, b_qkv);
    k_attn<<<NG * 2, 256, 11024 * 4>>>(pos, W_t, b_t, W_g, b_g);
    k_dense<<<NN / 16, 256, 34975 * 4>>>(W_d0, b_d0, W_d1, b_d1, W_d2, b_d2, out);
}

// round 4
// speedup vs baseline: 1.2229x; 1.0385x over previous
#include <cuda_runtime.h>
#include <math.h>

#define NG    64
#define ATOMS 32
#define NN    2048
#define HID   128
#define FEAT  64

// ---------------- scratch (device globals; no allocations allowed) ----------------
__device__ float d_isl[NG];
__device__ float d_x[NN * HID];
__device__ float d_q[NN * HID];
__device__ float d_k[NN * HID];
__device__ float d_v[NN * HID];
__device__ float d_vals[NN * HID];
__device__ float d_y0[NN * 128];
__device__ float d_y1[NN * 128];
// packed weights (k-major, zero-padded)
__device__ float d_Wq[128 * 384];    // qkv weight k-major
__device__ float d_Wp0[128 * 128];   // [k][o], o>=106 zero
__device__ float d_Wp1[128 * 128];   // [k][o], k>=106 or o>=85 zero
__device__ float d_Wp2[128 * 64];    // [k][o], k>=85 zero
__device__ float d_Bp0[128];
__device__ float d_Bp1[128];

// ---------------- K0: fused embedding + x = h * emb[batch] + 1/sqrt(len) -------
__global__ void k_prep(const float* __restrict__ h,
                       const float* __restrict__ next_type,
                       const float* __restrict__ W_emb,
                       const int* __restrict__ batch) {
    __shared__ float nt[FEAT];
    __shared__ float emb[HID];
    __shared__ int sc[256];
    int g = blockIdx.x, t = threadIdx.x;
    int base = g * ATOMS;

    if (t < FEAT) nt[t] = next_type[g * FEAT + t];
    __syncthreads();
    if (t < HID) {
        const float* w = W_emb + t * FEAT;
        float acc = 0.f;
#pragma unroll
        for (int f = 0; f < FEAT; f++) acc += nt[f] * w[f];
        emb[t] = acc;
    }
    int cnt = 0;
#pragma unroll
    for (int i = t; i < NN; i += 256) cnt += (batch[i] == g) ? 1 : 0;
    sc[t] = cnt;
    __syncthreads();
    for (int s = 128; s > 0; s >>= 1) {
        if (t < s) sc[t] += sc[t + s];
        __syncthreads();
    }
    if (t == 0) d_isl[g] = rsqrtf((float)sc[0]);

#pragma unroll
    for (int v = 0; v < 4; v++) {
        int lin = t + v * 256;
        int r = lin >> 5, kv = lin & 31;
        float4 hv = *(const float4*)&h[(base + r) * HID + kv * 4];
        float4 ev = *(const float4*)&emb[kv * 4];
        float4 o;
        o.x = hv.x * ev.x; o.y = hv.y * ev.y; o.z = hv.z * ev.z; o.w = hv.w * ev.w;
        *(float4*)&d_x[(base + r) * HID + kv * 4] = o;
    }
}

// ---------------- K0b: repack all weights k-major + zero-pad ----------------
// segments (dest-linear, coalesced writes):
//  [0, 49152)          d_Wq  [k*384+o]  <- Wqkv[o*128+k]
//  [49152, 65536)      d_Wp0 [k*128+o]  <- Wd0[o*128+k] if o<106 else 0
//  [65536, 81920)      d_Wp1 [k*128+o]  <- Wd1[o*106+k] if o<85 && k<106 else 0
//  [81920, 90112)      d_Wp2 [k*64+o]   <- Wd2[o*85+k]  if k<85 else 0
//  [90112, 90240)      d_Bp0 <- bd0 (pad 0)
//  [90240, 90368)      d_Bp1 <- bd1 (pad 0)
__global__ void k_repack(const float* __restrict__ Wqkv,
                         const float* __restrict__ Wd0, const float* __restrict__ bd0,
                         const float* __restrict__ Wd1, const float* __restrict__ bd1,
                         const float* __restrict__ Wd2) {
    int idx = blockIdx.x * 256 + threadIdx.x;
    if (idx < 49152) {
        int k = idx / 384, o = idx - k * 384;
        d_Wq[idx] = Wqkv[o * 128 + k];
    } else if (idx < 65536) {
        int e = idx - 49152;
        int k = e >> 7, o = e & 127;
        d_Wp0[e] = (o < 106) ? Wd0[o * 128 + k] : 0.f;
    } else if (idx < 81920) {
        int e = idx - 65536;
        int k = e >> 7, o = e & 127;
        d_Wp1[e] = (o < 85 && k < 106) ? Wd1[o * 106 + k] : 0.f;
    } else if (idx < 90112) {
        int e = idx - 81920;
        int k = e >> 6, o = e & 63;
        d_Wp2[e] = (k < 85) ? Wd2[o * 85 + k] : 0.f;
    } else if (idx < 90240) {
        int e = idx - 90112;
        d_Bp0[e] = (e < 106) ? bd0[e] : 0.f;
    } else if (idx < 90368) {
        int e = idx - 90240;
        d_Bp1[e] = (e < 85) ? bd1[e] : 0.f;
    }
}

// ---------------- K1: qkv = x @ Wq + b (64x64 tiles, conflict-free smem) -------
// dyn smem: Ws[64][64]=4096, As stride 66: 64 k x 66 = 4224 -> 8320 floats
__global__ void k_qkv(const float* __restrict__ b_qkv) {
    extern __shared__ float sm[];
    float* Ws = sm;          // [64][64] chunk of W, k-major
    float* As = sm + 4096;   // [64 k][66] (64 rows + pad 2)
    int tid = threadIdx.x;
    int rb = blockIdx.y * 64;
    int cb = blockIdx.x * 64;
    int ty = tid >> 4, tx = tid & 15;
    int r0 = ty * 4, c0 = tx * 4;
    float acc[4][4] = {};

    for (int k0 = 0; k0 < HID; k0 += 64) {
#pragma unroll
        for (int v = 0; v < 4; v++) {
            int lin = tid + v * 256;          // 1024 slots
            int r = lin >> 4, kq = lin & 15;
            float4 a = *(const float4*)&d_x[(rb + r) * HID + k0 + kq * 4];
            As[(kq * 4 + 0) * 66 + r] = a.x;
            As[(kq * 4 + 1) * 66 + r] = a.y;
            As[(kq * 4 + 2) * 66 + r] = a.z;
            As[(kq * 4 + 3) * 66 + r] = a.w;
            int k = lin >> 4, cq = lin & 15;
            *(float4*)&Ws[k * 64 + cq * 4] =
                *(const float4*)&d_Wq[(k0 + k) * 384 + cb + cq * 4];
        }
        __syncthreads();
#pragma unroll 4
        for (int k = 0; k < 64; k++) {
            float2 a01 = *(const float2*)&As[k * 66 + r0];
            float2 a23 = *(const float2*)&As[k * 66 + r0 + 2];
            float4 wv = *(const float4*)&Ws[k * 64 + c0];
            acc[0][0] += a01.x * wv.x; acc[0][1] += a01.x * wv.y;
            acc[0][2] += a01.x * wv.z; acc[0][3] += a01.x * wv.w;
            acc[1][0] += a01.y * wv.x; acc[1][1] += a01.y * wv.y;
            acc[1][2] += a01.y * wv.z; acc[1][3] += a01.y * wv.w;
            acc[2][0] += a23.x * wv.x; acc[2][1] += a23.x * wv.y;
            acc[2][2] += a23.x * wv.z; acc[2][3] += a23.x * wv.w;
            acc[3][0] += a23.y * wv.x; acc[3][1] += a23.y * wv.y;
            acc[3][2] += a23.y * wv.z; acc[3][3] += a23.y * wv.w;
        }
        __syncthreads();
    }

    int which = cb >> 7;
    int col0 = (cb & 127) + c0;
    float* outb = (which == 0) ? d_q : ((which == 1) ? d_k : d_v);
    float4 bv4;
    bv4.x = b_qkv[cb + c0 + 0];
    bv4.y = b_qkv[cb + c0 + 1];
    bv4.z = b_qkv[cb + c0 + 2];
    bv4.w = b_qkv[cb + c0 + 3];
#pragma unroll
    for (int i = 0; i < 4; i++) {
        float4 o;
        o.x = acc[i][0] + bv4.x;
        o.y = acc[i][1] + bv4.y;
        o.z = acc[i][2] + bv4.z;
        o.w = acc[i][3] + bv4.w;
        *(float4*)&outb[(rb + r0 + i) * HID + col0] = o;
    }
}

// ---------------- K2: fused attention, 2 blocks per graph (16 rows each) --------
__global__ void k_attn(const float* __restrict__ pos,
                       const float* __restrict__ W_t, const float* __restrict__ b_t,
                       const float* __restrict__ W_g, const float* __restrict__ b_g) {
    extern __shared__ float sm[];
    float* sQt  = sm;             // [128][16]
    float* sKt  = sm + 2048;      // [128][32]
    float* sV   = sm + 6144;      // [32][128]
    float* sL   = sm + 10240;     // [16][32]
    float* sWg  = sm + 10752;     // 128
    float* sPos = sm + 10880;     // 96
    float* sGate= sm + 10976;     // 16
    float* sWt  = sm + 10992;     // 32

    int bid = blockIdx.x, tid = threadIdx.x;
    int g = bid >> 1, half = bid & 1;
    int base = g * ATOMS;
    int rbase = half * 16;

#pragma unroll
    for (int v = 0; v < 2; v++) {
        int lin = tid + v * 256;
        int r = lin >> 5, kv = lin & 31;
        float4 qa = *(const float4*)&d_q[(base + rbase + r) * HID + kv * 4];
        sQt[(kv * 4 + 0) * 16 + r] = qa.x;
        sQt[(kv * 4 + 1) * 16 + r] = qa.y;
        sQt[(kv * 4 + 2) * 16 + r] = qa.z;
        sQt[(kv * 4 + 3) * 16 + r] = qa.w;
    }
#pragma unroll
    for (int v = 0; v < 4; v++) {
        int lin = tid + v * 256;
        int r = lin >> 5, kv = lin & 31;
        float4 ka = *(const float4*)&d_k[(base + r) * HID + kv * 4];
        sKt[(kv * 4 + 0) * 32 + r] = ka.x;
        sKt[(kv * 4 + 1) * 32 + r] = ka.y;
        sKt[(kv * 4 + 2) * 32 + r] = ka.z;
        sKt[(kv * 4 + 3) * 32 + r] = ka.w;
        *(float4*)&sV[r * 128 + kv * 4] = *(const float4*)&d_v[(base + r) * HID + kv * 4];
    }
    if (tid < 128) sWg[tid] = W_g[tid];
    if (tid < 96) sPos[tid] = pos[base * 3 + tid];
    if (tid < 32) sWt[tid] = W_t[tid];
    __syncthreads();

    int w = tid >> 5, lane = tid & 31;
    float invs = d_isl[g];
    float bgv = b_g[0];

#pragma unroll
    for (int rr = 0; rr < 2; rr++) {
        int row = w * 2 + rr;
        const float* xr = d_x + (base + rbase + row) * HID;
        float p = 0.f;
#pragma unroll
        for (int k = lane; k < HID; k += 32) p += xr[k] * sWg[k];
#pragma unroll
        for (int o = 16; o; o >>= 1) p += __shfl_xor_sync(~0u, p, o);
        if (lane == 0) sGate[row] = 1.f / (1.f + __expf(-(p + bgv)));
    }

    int i = tid >> 4;
    int j0 = (tid & 15) * 2;
    float qk0 = 0.f, qk1 = 0.f;
#pragma unroll 8
    for (int k = 0; k < HID; k++) {
        float qa = sQt[k * 16 + i];
        float2 kb = *(const float2*)&sKt[k * 32 + j0];
        qk0 += qa * kb.x;
        qk1 += qa * kb.y;
    }
    float btv = b_t[0];
    int gi = rbase + i;
    float px = sPos[gi * 3 + 0], py = sPos[gi * 3 + 1], pz = sPos[gi * 3 + 2];
    const float step = 10.f / 31.f;
    float qkp[2] = {qk0, qk1};
#pragma unroll
    for (int jj = 0; jj < 2; jj++) {
        int j = j0 + jj;
        float dx = px - sPos[j * 3 + 0];
        float dy = py - sPos[j * 3 + 1];
        float dz = pz - sPos[j * 3 + 2];
        float d = sqrtf(fmaxf(dx * dx + dy * dy + dz * dz, 1e-12f));
        int b0 = __float2int_rn(d * (31.f / 10.f));
        int bs = min(max(b0 - 4, 0), 24);
        float t = btv;
#pragma unroll
        for (int bb = 0; bb < 8; bb++) {
            int b = bs + bb;
            float diff = d - (float)b * step;
            t += __expf(-10.f * diff * diff) * sWt[b];
        }
        sL[i * 32 + j] = qkp[jj] * invs + t;
    }
    __syncthreads();

#pragma unroll
    for (int rr = 0; rr < 2; rr++) {
        int r = w * 2 + rr;
        float vv = sL[r * 32 + lane];
        float m = vv;
#pragma unroll
        for (int o = 16; o; o >>= 1) m = fmaxf(m, __shfl_xor_sync(~0u, m, o));
        float e = __expf(vv - m);
        float s = e;
#pragma unroll
        for (int o = 16; o; o >>= 1) s += __shfl_xor_sync(~0u, s, o);
        sL[r * 32 + lane] = e / s;
    }
    __syncthreads();

    int rg = tid >> 5, cg = tid & 31;
    int ir = rg * 2, c0 = cg * 4;
    float a00 = 0.f, a01 = 0.f, a02 = 0.f, a03 = 0.f;
    float a10 = 0.f, a11 = 0.f, a12 = 0.f, a13 = 0.f;
#pragma unroll 8
    for (int j = 0; j < 32; j++) {
        float p0 = sL[ir * 32 + j];
        float p1 = sL[(ir + 1) * 32 + j];
        float4 vv = *(const float4*)&sV[j * 128 + c0];
        a00 += p0 * vv.x; a01 += p0 * vv.y; a02 += p0 * vv.z; a03 += p0 * vv.w;
        a10 += p1 * vv.x; a11 += p1 * vv.y; a12 += p1 * vv.z; a13 += p1 * vv.w;
    }
    {
        int grow = base + rbase + ir;
        float gg = sGate[ir];
        float4 xr = *(const float4*)&d_x[grow * HID + c0];
        float4 o;
        o.x = a00 * gg + xr.x; o.y = a01 * gg + xr.y;
        o.z = a02 * gg + xr.z; o.w = a03 * gg + xr.w;
        *(float4*)&d_vals[grow * HID + c0] = o;
        gg = sGate[ir + 1];
        xr = *(const float4*)&d_x[(grow + 1) * HID + c0];
        o.x = a10 * gg + xr.x; o.y = a11 * gg + xr.y;
        o.z = a12 * gg + xr.z; o.w = a13 * gg + xr.w;
        *(float4*)&d_vals[(grow + 1) * HID + c0] = o;
    }
}

// ---------------- K3: dense layer GEMM (32 rows x 64 cols per block) -----------
// ACT: 0 = SiLU, 1 = none + fused log_softmax (requires CS==64, gridDim.x==1)
// dyn smem: Ws[128][64]=8192, As[128][34]=4352, Bs 64 -> 12608 floats (50432 B)
template<int WS, int CS, int ACT>
__global__ void k_mlp(const float* __restrict__ A, const float* __restrict__ Wp,
                      const float* __restrict__ Bp, float* __restrict__ C) {
    extern __shared__ float sm[];
    float* Ws = sm;            // [128][64]
    float* As = sm + 8192;     // [128 k][34] (32 rows + pad 2)
    float* Bs = sm + 12544;    // 64
    int tid = threadIdx.x;
    int rb = blockIdx.y * 32;
    int cb = blockIdx.x * 64;

    // stage W: 2048 float4 slots
#pragma unroll
    for (int v = 0; v < 8; v++) {
        int lin = tid + v * 256;
        int k = lin >> 4, cq = lin & 15;
        *(float4*)&Ws[k * 64 + cq * 4] = *(const float4*)&Wp[k * WS + cb + cq * 4];
    }
    // stage A (k-major): 1024 float4 slots
#pragma unroll
    for (int v = 0; v < 4; v++) {
        int lin = tid + v * 256;
        int r = lin >> 5, kq = lin & 31;
        float4 a = *(const float4*)&A[(rb + r) * 128 + kq * 4];
        As[(kq * 4 + 0) * 34 + r] = a.x;
        As[(kq * 4 + 1) * 34 + r] = a.y;
        As[(kq * 4 + 2) * 34 + r] = a.z;
        As[(kq * 4 + 3) * 34 + r] = a.w;
    }
    if (tid < 64) Bs[tid] = Bp[cb + tid];
    __syncthreads();

    int ty = tid >> 4, tx = tid & 15;
    int r0 = ty * 2, c0 = tx * 4;
    float acc[2][4] = {};
#pragma unroll 4
    for (int k = 0; k < 128; k++) {
        float2 a01 = *(const float2*)&As[k * 34 + r0];
        float4 wv = *(const float4*)&Ws[k * 64 + c0];
        acc[0][0] += a01.x * wv.x; acc[0][1] += a01.x * wv.y;
        acc[0][2] += a01.x * wv.z; acc[0][3] += a01.x * wv.w;
        acc[1][0] += a01.y * wv.x; acc[1][1] += a01.y * wv.y;
        acc[1][2] += a01.y * wv.z; acc[1][3] += a01.y * wv.w;
    }

    if (ACT == 0) {
#pragma unroll
        for (int rr = 0; rr < 2; rr++) {
            float4 o;
            float z;
            z = acc[rr][0] + Bs[c0 + 0]; o.x = z / (1.f + __expf(-z));
            z = acc[rr][1] + Bs[c0 + 1]; o.y = z / (1.f + __expf(-z));
            z = acc[rr][2] + Bs[c0 + 2]; o.z = z / (1.f + __expf(-z));
            z = acc[rr][3] + Bs[c0 + 3]; o.w = z / (1.f + __expf(-z));
            *(float4*)&C[(rb + r0 + rr) * CS + cb + c0] = o;
        }
    } else {
        float* sY = As;   // reuse (2048 floats needed, As has 4352)
        __syncthreads();  // all As reads done before overwrite
#pragma unroll
        for (int rr = 0; rr < 2; rr++) {
            float4 o;
            o.x = acc[rr][0] + Bs[c0 + 0];
            o.y = acc[rr][1] + Bs[c0 + 1];
            o.z = acc[rr][2] + Bs[c0 + 2];
            o.w = acc[rr][3] + Bs[c0 + 3];
            *(float4*)&sY[(r0 + rr) * 64 + c0] = o;
        }
        __syncthreads();
        int w = tid >> 5, lane = tid & 31;
#pragma unroll
        for (int rr = 0; rr < 4; rr++) {
            int r = w * 4 + rr;
            float v0 = sY[r * 64 + lane];
            float v1 = sY[r * 64 + 32 + lane];
            float m = fmaxf(v0, v1);
#pragma unroll
            for (int o = 16; o; o >>= 1) m = fmaxf(m, __shfl_xor_sync(~0u, m, o));
            float s = __expf(v0 - m) + __expf(v1 - m);
#pragma unroll
            for (int o = 16; o; o >>= 1) s += __shfl_xor_sync(~0u, s, o);
            float ls = logf(s) + m;
            C[(rb + r) * 64 + lane] = v0 - ls;
            C[(rb + r) * 64 + 32 + lane] = v1 - ls;
        }
    }
}

// ---------------- launch ----------------
extern "C" void kernel_launch(void* const* d_in, const int* in_sizes, int n_in,
                              void* d_out, int out_size) {
    const float* h     = (const float*)d_in[0];
    const float* pos   = (const float*)d_in[1];
    const float* nt    = (const float*)d_in[2];
    const int*   batch = (const int*)d_in[3];
    const float* W_emb = (const float*)d_in[4];
    const float* W_qkv = (const float*)d_in[5];
    const float* b_qkv = (const float*)d_in[6];
    // d_in[7]=W_b, d_in[8]=b_b : per-row bias, drops out of softmax
    const float* W_g   = (const float*)d_in[9];
    const float* b_g   = (const float*)d_in[10];
    const float* W_t   = (const float*)d_in[11];
    const float* b_t   = (const float*)d_in[12];
    const float* W_d0  = (const float*)d_in[13];
    const float* b_d0  = (const float*)d_in[14];
    const float* W_d1  = (const float*)d_in[15];
    const float* b_d1  = (const float*)d_in[16];
    const float* W_d2  = (const float*)d_in[17];
    const float* b_d2  = (const float*)d_in[18];
    float* out = (float*)d_out;

    float *p_y0, *p_y1, *p_Wq, *p_Wp0, *p_Wp1, *p_Wp2, *p_Bp0, *p_Bp1;
    cudaGetSymbolAddress((void**)&p_y0, d_y0);
    cudaGetSymbolAddress((void**)&p_y1, d_y1);
    cudaGetSymbolAddress((void**)&p_Wq, d_Wq);
    cudaGetSymbolAddress((void**)&p_Wp0, d_Wp0);
    cudaGetSymbolAddress((void**)&p_Wp1, d_Wp1);
    cudaGetSymbolAddress((void**)&p_Wp2, d_Wp2);
    cudaGetSymbolAddress((void**)&p_Bp0, d_Bp0);
    cudaGetSymbolAddress((void**)&p_Bp1, d_Bp1);
    float* p_vals;
    cudaGetSymbolAddress((void**)&p_vals, d_vals);

    cudaFuncSetAttribute(k_attn, cudaFuncAttributeMaxDynamicSharedMemorySize, 48 * 1024);
    cudaFuncSetAttribute(k_mlp<128, 128, 0>, cudaFuncAttributeMaxDynamicSharedMemorySize, 52 * 1024);
    cudaFuncSetAttribute(k_mlp<64, 64, 1>, cudaFuncAttributeMaxDynamicSharedMemorySize, 52 * 1024);

    k_repack<<<354, 256>>>(W_qkv, W_d0, b_d0, W_d1, b_d1, W_d2);
    k_prep<<<NG, 256>>>(h, nt, W_emb, batch);
    k_qkv<<<dim3(6, 32), 256, 8320 * 4>>>(b_qkv);
    k_attn<<<NG * 2, 256, 11024 * 4>>>(pos, W_t, b_t, W_g, b_g);
    k_mlp<128, 128, 0><<<dim3(2, 64), 256, 12608 * 4>>>(p_vals, p_Wp0, p_Bp0, p_y0);
    k_mlp<128, 128, 0><<<dim3(2, 64), 256, 12608 * 4>>>(p_y0, p_Wp1, p_Bp1, p_y1);
    k_mlp<64, 64, 1><<<dim3(1, 64), 256, 12608 * 4>>>(p_y1, p_Wp2, b_d2, out);
}

// round 5
// speedup vs baseline: 1.2774x; 1.0446x over previous
#include <cuda_runtime.h>
#include <math.h>

#define NG    64
#define ATOMS 32
#define NN    2048
#define HID   128
#define FEAT  64

// ---------------- scratch (device globals; no allocations allowed) ----------------
__device__ float d_isl[NG];
__device__ float d_x[NN * HID];
__device__ float d_q[NN * HID];
__device__ float d_k[NN * HID];
__device__ float d_v[NN * HID];
__device__ float d_vals[NN * HID];
// packed weights (k-major, zero-padded)
__device__ float d_Wq[128 * 384];
__device__ float d_Wp0[128 * 128];   // [k][o], o>=106 zero
__device__ float d_Wp1[128 * 128];   // [k][o], k>=106 or o>=85 zero
__device__ float d_Wp2[128 * 64];    // [k][o], k>=85 zero
__device__ float d_Bp0[128];
__device__ float d_Bp1[128];

// ---------------- K0: setup = prep (blocks 0..63) + repack (blocks 64..417) ----
__global__ void k_setup(const float* __restrict__ h,
                        const float* __restrict__ next_type,
                        const float* __restrict__ W_emb,
                        const int* __restrict__ batch,
                        const float* __restrict__ Wqkv,
                        const float* __restrict__ Wd0, const float* __restrict__ bd0,
                        const float* __restrict__ Wd1, const float* __restrict__ bd1,
                        const float* __restrict__ Wd2) {
    int b = blockIdx.x, t = threadIdx.x;
    if (b < NG) {
        __shared__ float nt[FEAT];
        __shared__ float emb[HID];
        __shared__ int sc[256];
        int g = b;
        int base = g * ATOMS;
        if (t < FEAT) nt[t] = next_type[g * FEAT + t];
        __syncthreads();
        if (t < HID) {
            const float* w = W_emb + t * FEAT;
            float acc = 0.f;
#pragma unroll
            for (int f = 0; f < FEAT; f++) acc += nt[f] * w[f];
            emb[t] = acc;
        }
        int cnt = 0;
#pragma unroll
        for (int i = t; i < NN; i += 256) cnt += (batch[i] == g) ? 1 : 0;
        sc[t] = cnt;
        __syncthreads();
        for (int s = 128; s > 0; s >>= 1) {
            if (t < s) sc[t] += sc[t + s];
            __syncthreads();
        }
        if (t == 0) d_isl[g] = rsqrtf((float)sc[0]);
#pragma unroll
        for (int v = 0; v < 4; v++) {
            int lin = t + v * 256;
            int r = lin >> 5, kv = lin & 31;
            float4 hv = *(const float4*)&h[(base + r) * HID + kv * 4];
            float4 ev = *(const float4*)&emb[kv * 4];
            float4 o;
            o.x = hv.x * ev.x; o.y = hv.y * ev.y; o.z = hv.z * ev.z; o.w = hv.w * ev.w;
            *(float4*)&d_x[(base + r) * HID + kv * 4] = o;
        }
    } else {
        int idx = (b - NG) * 256 + t;
        if (idx < 49152) {
            int k = idx / 384, o = idx - k * 384;
            d_Wq[idx] = Wqkv[o * 128 + k];
        } else if (idx < 65536) {
            int e = idx - 49152;
            int k = e >> 7, o = e & 127;
            d_Wp0[e] = (o < 106) ? Wd0[o * 128 + k] : 0.f;
        } else if (idx < 81920) {
            int e = idx - 65536;
            int k = e >> 7, o = e & 127;
            d_Wp1[e] = (o < 85 && k < 106) ? Wd1[o * 106 + k] : 0.f;
        } else if (idx < 90112) {
            int e = idx - 81920;
            int k = e >> 6, o = e & 63;
            d_Wp2[e] = (k < 85) ? Wd2[o * 85 + k] : 0.f;
        } else if (idx < 90240) {
            int e = idx - 90112;
            d_Bp0[e] = (e < 106) ? bd0[e] : 0.f;
        } else if (idx < 90368) {
            int e = idx - 90240;
            d_Bp1[e] = (e < 85) ? bd1[e] : 0.f;
        }
    }
}

// ---------------- K1: qkv = x @ Wq + b (64x64 tiles) ----------------
// dyn smem: Ws[64][64]=4096, As[64 k][66]=4224 -> 8320 floats
__global__ void k_qkv(const float* __restrict__ b_qkv) {
    extern __shared__ float sm[];
    float* Ws = sm;
    float* As = sm + 4096;
    int tid = threadIdx.x;
    int rb = blockIdx.y * 64;
    int cb = blockIdx.x * 64;
    int ty = tid >> 4, tx = tid & 15;
    int r0 = ty * 4, c0 = tx * 4;
    float acc[4][4] = {};

    for (int k0 = 0; k0 < HID; k0 += 64) {
        // A: row index lane-varying -> conflict-free k-major STS
#pragma unroll
        for (int v = 0; v < 4; v++) {
            int lin = tid + v * 256;           // 1024 slots
            int r = lin & 63, kq = lin >> 6;   // kq 0..15
            float4 a = *(const float4*)&d_x[(rb + r) * HID + k0 + kq * 4];
            As[(kq * 4 + 0) * 66 + r] = a.x;
            As[(kq * 4 + 1) * 66 + r] = a.y;
            As[(kq * 4 + 2) * 66 + r] = a.z;
            As[(kq * 4 + 3) * 66 + r] = a.w;
        }
        // W: linear float4 copy
#pragma unroll
        for (int v = 0; v < 4; v++) {
            int lin = tid + v * 256;
            int k = lin >> 4, cq = lin & 15;
            *(float4*)&Ws[k * 64 + cq * 4] =
                *(const float4*)&d_Wq[(k0 + k) * 384 + cb + cq * 4];
        }
        __syncthreads();
#pragma unroll 4
        for (int k = 0; k < 64; k++) {
            float2 a01 = *(const float2*)&As[k * 66 + r0];
            float2 a23 = *(const float2*)&As[k * 66 + r0 + 2];
            float4 wv = *(const float4*)&Ws[k * 64 + c0];
            acc[0][0] += a01.x * wv.x; acc[0][1] += a01.x * wv.y;
            acc[0][2] += a01.x * wv.z; acc[0][3] += a01.x * wv.w;
            acc[1][0] += a01.y * wv.x; acc[1][1] += a01.y * wv.y;
            acc[1][2] += a01.y * wv.z; acc[1][3] += a01.y * wv.w;
            acc[2][0] += a23.x * wv.x; acc[2][1] += a23.x * wv.y;
            acc[2][2] += a23.x * wv.z; acc[2][3] += a23.x * wv.w;
            acc[3][0] += a23.y * wv.x; acc[3][1] += a23.y * wv.y;
            acc[3][2] += a23.y * wv.z; acc[3][3] += a23.y * wv.w;
        }
        __syncthreads();
    }

    int which = cb >> 7;
    int col0 = (cb & 127) + c0;
    float* outb = (which == 0) ? d_q : ((which == 1) ? d_k : d_v);
    float4 bv4;
    bv4.x = b_qkv[cb + c0 + 0];
    bv4.y = b_qkv[cb + c0 + 1];
    bv4.z = b_qkv[cb + c0 + 2];
    bv4.w = b_qkv[cb + c0 + 3];
#pragma unroll
    for (int i = 0; i < 4; i++) {
        float4 o;
        o.x = acc[i][0] + bv4.x;
        o.y = acc[i][1] + bv4.y;
        o.z = acc[i][2] + bv4.z;
        o.w = acc[i][3] + bv4.w;
        *(float4*)&outb[(rb + r0 + i) * HID + col0] = o;
    }
}

// ---------------- K2: fused attention, 4 blocks per graph (8 rows each) --------
// smem floats: sQt[128][9]=1152, sKt[128][32]=4096, sV[32][128]=4096, sL[8][32]=256,
//              sWg 128, sPos 96, sGate 8, sWt 32 -> 9864 floats (~39 KB, 2 blocks/SM)
__global__ void k_attn(const float* __restrict__ pos,
                       const float* __restrict__ W_t, const float* __restrict__ b_t,
                       const float* __restrict__ W_g, const float* __restrict__ b_g) {
    extern __shared__ float sm[];
    float* sQt  = sm;             // [128][9]
    float* sKt  = sm + 1152;      // [128][32]
    float* sV   = sm + 5248;      // [32][128]
    float* sL   = sm + 9344;      // [8][32]
    float* sWg  = sm + 9600;      // 128
    float* sPos = sm + 9728;      // 96
    float* sGate= sm + 9824;      // 8
    float* sWt  = sm + 9832;      // 32

    int bid = blockIdx.x, tid = threadIdx.x;
    int g = bid >> 2, quarter = bid & 3;
    int base = g * ATOMS;
    int rbase = quarter * 8;

    // Q (8 rows, k-major, stride 9): 256 slots, 1/thread, row lane-varying
    {
        int kq = tid >> 3, r = tid & 7;
        float4 qa = *(const float4*)&d_q[(base + rbase + r) * HID + kq * 4];
        sQt[(kq * 4 + 0) * 9 + r] = qa.x;
        sQt[(kq * 4 + 1) * 9 + r] = qa.y;
        sQt[(kq * 4 + 2) * 9 + r] = qa.z;
        sQt[(kq * 4 + 3) * 9 + r] = qa.w;
    }
    // K (32 rows, k-major): 1024 slots, 4/thread, row lane-varying -> bank=lane
#pragma unroll
    for (int v = 0; v < 4; v++) {
        int lin = tid + v * 256;
        int r = lin & 31, kq = lin >> 5;
        float4 ka = *(const float4*)&d_k[(base + r) * HID + kq * 4];
        sKt[(kq * 4 + 0) * 32 + r] = ka.x;
        sKt[(kq * 4 + 1) * 32 + r] = ka.y;
        sKt[(kq * 4 + 2) * 32 + r] = ka.z;
        sKt[(kq * 4 + 3) * 32 + r] = ka.w;
    }
    // V row-major: coalesced float4, conflict-free
#pragma unroll
    for (int v = 0; v < 4; v++) {
        int lin = tid + v * 256;
        int r = lin >> 5, kv = lin & 31;
        *(float4*)&sV[r * 128 + kv * 4] = *(const float4*)&d_v[(base + r) * HID + kv * 4];
    }
    if (tid < 128) sWg[tid] = W_g[tid];
    if (tid < 96) sPos[tid] = pos[base * 3 + tid];
    if (tid < 32) sWt[tid] = W_t[tid];
    __syncthreads();

    int w = tid >> 5, lane = tid & 31;
    float invs = d_isl[g];
    float bgv = b_g[0];

    // gate: warp w -> local row w
    {
        const float* xr = d_x + (base + rbase + w) * HID;
        float p = 0.f;
#pragma unroll
        for (int k = lane; k < HID; k += 32) p += xr[k] * sWg[k];
#pragma unroll
        for (int o = 16; o; o >>= 1) p += __shfl_xor_sync(~0u, p, o);
        if (lane == 0) sGate[w] = 1.f / (1.f + __expf(-(p + bgv)));
    }

    // logits: thread -> (i = tid>>5, j = lane), two accumulator chains
    int i = tid >> 5;
    int j = lane;
    float qk_e = 0.f, qk_o = 0.f;
#pragma unroll 8
    for (int k = 0; k < HID; k += 2) {
        qk_e += sQt[k * 9 + i] * sKt[k * 32 + j];
        qk_o += sQt[(k + 1) * 9 + i] * sKt[(k + 1) * 32 + j];
    }
    float qk = qk_e + qk_o;
    float btv = b_t[0];
    int gi = rbase + i;
    float dx = sPos[gi * 3 + 0] - sPos[j * 3 + 0];
    float dy = sPos[gi * 3 + 1] - sPos[j * 3 + 1];
    float dz = sPos[gi * 3 + 2] - sPos[j * 3 + 2];
    float d = sqrtf(fmaxf(dx * dx + dy * dy + dz * dz, 1e-12f));
    const float step = 10.f / 31.f;
    // 8-bin window around nearest center (dropped bins < 3e-6 weight)
    int b0 = __float2int_rn(d * (31.f / 10.f));
    int bs = min(max(b0 - 4, 0), 24);
    float t = btv;
#pragma unroll
    for (int bb = 0; bb < 8; bb++) {
        int b = bs + bb;
        float diff = d - (float)b * step;
        t += __expf(-10.f * diff * diff) * sWt[b];
    }
    sL[i * 32 + j] = qk * invs + t;
    __syncthreads();

    // softmax: warp w -> row w
    {
        float vv = sL[w * 32 + lane];
        float m = vv;
#pragma unroll
        for (int o = 16; o; o >>= 1) m = fmaxf(m, __shfl_xor_sync(~0u, m, o));
        float e = __expf(vv - m);
        float s = e;
#pragma unroll
        for (int o = 16; o; o >>= 1) s += __shfl_xor_sync(~0u, s, o);
        sL[w * 32 + lane] = e / s;
    }
    __syncthreads();

    // out = (attn @ V) * gate + x : 1 row x 4 cols per thread
    {
        int rg = tid >> 5, cg = tid & 31;
        int c0 = cg * 4;
        float a0 = 0.f, a1 = 0.f, a2 = 0.f, a3 = 0.f;
#pragma unroll 8
        for (int jj = 0; jj < 32; jj++) {
            float p = sL[rg * 32 + jj];
            float4 vv = *(const float4*)&sV[jj * 128 + c0];
            a0 += p * vv.x; a1 += p * vv.y; a2 += p * vv.z; a3 += p * vv.w;
        }
        int grow = base + rbase + rg;
        float gg = sGate[rg];
        float4 xr = *(const float4*)&d_x[grow * HID + c0];
        float4 o;
        o.x = a0 * gg + xr.x; o.y = a1 * gg + xr.y;
        o.z = a2 * gg + xr.z; o.w = a3 * gg + xr.w;
        *(float4*)&d_vals[grow * HID + c0] = o;
    }
}

// ---------------- K3: fused dense head (3 layers + log_softmax), 16 rows/block --
// smem floats: W0 16384 @0, W1 13568 @16384, W2 5440 @29952, As 2304 @35392,
// Y0 1908 @37696, Y1 1530 @39604, Y2 1024 @41136, B0 @42160, B1 @42288, B2 @42416
// total 42480 floats = 169920 B
__global__ void k_dense(const float* __restrict__ bd2, float* __restrict__ out) {
    extern __shared__ float sm[];
    float* W0 = sm;
    float* W1 = sm + 16384;
    float* W2 = sm + 29952;
    float* As = sm + 35392;   // [128 k][18]
    float* Y0 = sm + 37696;   // [106][18]
    float* Y1 = sm + 39604;   // [85][18]
    float* Y2 = sm + 41136;   // [16][64]
    float* B0 = sm + 42160;
    float* B1 = sm + 42288;
    float* B2 = sm + 42416;

    int tid = threadIdx.x;
    int rb = blockIdx.x * 16;

    // linear float4 weight copies (packed k-major already)
    {
        const float4* s = (const float4*)d_Wp0;
        float4* dst = (float4*)W0;
        for (int i = tid; i < 4096; i += 256) dst[i] = s[i];
        s = (const float4*)d_Wp1;
        dst = (float4*)W1;
        for (int i = tid; i < 3392; i += 256) dst[i] = s[i];   // first 106 rows
        s = (const float4*)d_Wp2;
        dst = (float4*)W2;
        for (int i = tid; i < 1360; i += 256) dst[i] = s[i];   // first 85 rows
    }
    // A (16 rows, k-major stride 18): 512 slots, row lane-varying
#pragma unroll
    for (int v = 0; v < 2; v++) {
        int lin = tid + v * 256;
        int r = lin & 15, kq = lin >> 4;
        float4 a = *(const float4*)&d_vals[(rb + r) * 128 + kq * 4];
        As[(kq * 4 + 0) * 18 + r] = a.x;
        As[(kq * 4 + 1) * 18 + r] = a.y;
        As[(kq * 4 + 2) * 18 + r] = a.z;
        As[(kq * 4 + 3) * 18 + r] = a.w;
    }
    if (tid < 128) B0[tid] = d_Bp0[tid];
    if (tid < 128) B1[tid] = d_Bp1[tid];
    if (tid < 64) B2[tid] = bd2[tid];
    __syncthreads();

    int ty = tid >> 5, tx = tid & 31;
    int r0 = ty * 2, c0 = tx * 4;

    // layer 0: 128 -> 128(pad) SiLU, store Y0 k-major (o<106)
    {
        float acc[2][4] = {};
#pragma unroll 4
        for (int k = 0; k < 128; k++) {
            float2 a01 = *(const float2*)&As[k * 18 + r0];
            float4 wv = *(const float4*)&W0[k * 128 + c0];
            acc[0][0] += a01.x * wv.x; acc[0][1] += a01.x * wv.y;
            acc[0][2] += a01.x * wv.z; acc[0][3] += a01.x * wv.w;
            acc[1][0] += a01.y * wv.x; acc[1][1] += a01.y * wv.y;
            acc[1][2] += a01.y * wv.z; acc[1][3] += a01.y * wv.w;
        }
#pragma unroll
        for (int rr = 0; rr < 2; rr++)
#pragma unroll
            for (int cc = 0; cc < 4; cc++) {
                int o = c0 + cc;
                if (o < 106) {
                    float z = acc[rr][cc] + B0[o];
                    Y0[o * 18 + r0 + rr] = z / (1.f + __expf(-z));
                }
            }
    }
    __syncthreads();

    // layer 1: 106 -> 128(pad) SiLU, store Y1 k-major (o<85)
    {
        float acc[2][4] = {};
#pragma unroll 2
        for (int k = 0; k < 106; k++) {
            float2 a01 = *(const float2*)&Y0[k * 18 + r0];
            float4 wv = *(const float4*)&W1[k * 128 + c0];
            acc[0][0] += a01.x * wv.x; acc[0][1] += a01.x * wv.y;
            acc[0][2] += a01.x * wv.z; acc[0][3] += a01.x * wv.w;
            acc[1][0] += a01.y * wv.x; acc[1][1] += a01.y * wv.y;
            acc[1][2] += a01.y * wv.z; acc[1][3] += a01.y * wv.w;
        }
#pragma unroll
        for (int rr = 0; rr < 2; rr++)
#pragma unroll
            for (int cc = 0; cc < 4; cc++) {
                int o = c0 + cc;
                if (o < 85) {
                    float z = acc[rr][cc] + B1[o];
                    Y1[o * 18 + r0 + rr] = z / (1.f + __expf(-z));
                }
            }
    }
    __syncthreads();

    // layer 2: 85 -> 64 linear, Y2 row-major
    {
        int rg = tid >> 4, cg = tid & 15;
        int cc0 = cg * 4;
        float a0 = 0.f, a1 = 0.f, a2 = 0.f, a3 = 0.f;
#pragma unroll 5
        for (int k = 0; k < 85; k++) {
            float av = Y1[k * 18 + rg];
            float4 wv = *(const float4*)&W2[k * 64 + cc0];
            a0 += av * wv.x; a1 += av * wv.y; a2 += av * wv.z; a3 += av * wv.w;
        }
        float4 o;
        o.x = a0 + B2[cc0 + 0];
        o.y = a1 + B2[cc0 + 1];
        o.z = a2 + B2[cc0 + 2];
        o.w = a3 + B2[cc0 + 3];
        *(float4*)&Y2[rg * 64 + cc0] = o;
    }
    __syncthreads();

    // log_softmax: 8 warps x 2 rows
    int w = tid >> 5, lane = tid & 31;
#pragma unroll
    for (int rr = 0; rr < 2; rr++) {
        int r = w * 2 + rr;
        float v0 = Y2[r * 64 + lane];
        float v1 = Y2[r * 64 + 32 + lane];
        float m = fmaxf(v0, v1);
#pragma unroll
        for (int o = 16; o; o >>= 1) m = fmaxf(m, __shfl_xor_sync(~0u, m, o));
        float s = __expf(v0 - m) + __expf(v1 - m);
#pragma unroll
        for (int o = 16; o; o >>= 1) s += __shfl_xor_sync(~0u, s, o);
        float ls = logf(s) + m;
        out[(rb + r) * 64 + lane] = v0 - ls;
        out[(rb + r) * 64 + 32 + lane] = v1 - ls;
    }
}

// ---------------- launch ----------------
extern "C" void kernel_launch(void* const* d_in, const int* in_sizes, int n_in,
                              void* d_out, int out_size) {
    const float* h     = (const float*)d_in[0];
    const float* pos   = (const float*)d_in[1];
    const float* nt    = (const float*)d_in[2];
    const int*   batch = (const int*)d_in[3];
    const float* W_emb = (const float*)d_in[4];
    const float* W_qkv = (const float*)d_in[5];
    const float* b_qkv = (const float*)d_in[6];
    // d_in[7]=W_b, d_in[8]=b_b : per-row bias, drops out of softmax
    const float* W_g   = (const float*)d_in[9];
    const float* b_g   = (const float*)d_in[10];
    const float* W_t   = (const float*)d_in[11];
    const float* b_t   = (const float*)d_in[12];
    const float* W_d0  = (const float*)d_in[13];
    const float* b_d0  = (const float*)d_in[14];
    const float* W_d1  = (const float*)d_in[15];
    const float* b_d1  = (const float*)d_in[16];
    const float* W_d2  = (const float*)d_in[17];
    const float* b_d2  = (const float*)d_in[18];
    float* out = (float*)d_out;

    cudaFuncSetAttribute(k_attn, cudaFuncAttributeMaxDynamicSharedMemorySize, 48 * 1024);
    cudaFuncSetAttribute(k_dense, cudaFuncAttributeMaxDynamicSharedMemorySize, 176 * 1024);

    k_setup<<<NG + 354, 256>>>(h, nt, W_emb, batch, W_qkv, W_d0, b_d0, W_d1, b_d1, W_d2);
    k_qkv<<<dim3(6, 32), 256, 8320 * 4>>>(b_qkv);
    k_attn<<<NG * 4, 256, 9864 * 4>>>(pos, W_t, b_t, W_g, b_g);
    k_dense<<<NN / 16, 256, 42480 * 4>>>(b_d2, out);
}